// round 1
// baseline (speedup 1.0000x reference)
#include <cuda_runtime.h>

#define NN 50000
#define EE 800000
#define GG 50
#define MROW 164
#define HROW 72
#define XROW 132

typedef unsigned long long ull;

// -------- persistent device scratch (no runtime allocation allowed) --------
__device__ float g_x[NN * 64];        // node state h (starts as input x)
__device__ float g_c[NN * 64];        // LSTM cell state
__device__ float g_a[NN * 64];        // aggregated messages
__device__ float g_gates[NN * 256];   // LSTM pre-activations scratch
__device__ int   g_idx64;             // 1 if edge_index is int64, 0 if int32

// -------- packed f32x2 helpers (FFMA2: 2x fp32 FMA rate on sm_103a) --------
__device__ __forceinline__ ull dup2(float x) {
    ull r; asm("mov.b64 %0, {%1,%1};" : "=l"(r) : "f"(x)); return r;
}
__device__ __forceinline__ ull pack2f(float x, float y) {
    ull r; asm("mov.b64 %0, {%1,%2};" : "=l"(r) : "f"(x), "f"(y)); return r;
}
__device__ __forceinline__ void fma2(ull& d, ull a, ull b) {
    asm("fma.rn.f32x2 %0, %1, %2, %0;" : "+l"(d) : "l"(a), "l"(b));
}
__device__ __forceinline__ float2 unpack2(ull v) {
    float lo, hi; asm("mov.b64 {%0,%1}, %2;" : "=f"(lo), "=f"(hi) : "l"(v));
    return make_float2(lo, hi);
}

__device__ __forceinline__ float sigf(float x) { return 1.f / (1.f + __expf(-x)); }
__device__ __forceinline__ float tanh_f(float x) {
    float t = __expf(-2.f * fabsf(x));
    float r = (1.f - t) / (1.f + t);
    return copysignf(r, x);
}

// -------- dtype detection for edge_index (int64 vs silently-int32) --------
__global__ void detect_kernel(const int* __restrict__ raw) {
    if (threadIdx.x == 0 && blockIdx.x == 0) {
        int z = 0;
        for (int i = 1; i < 2048; i += 2) z += (raw[i] == 0);
        g_idx64 = (z > 512) ? 1 : 0;
    }
}

// -------- init: copy x -> g_x, zero g_c, zero d_out --------
__global__ void init_kernel(const float4* __restrict__ x, float* __restrict__ out) {
    int i = blockIdx.x * blockDim.x + threadIdx.x;
    if (i < NN * 16) {
        ((float4*)g_x)[i] = x[i];
        ((float4*)g_c)[i] = make_float4(0.f, 0.f, 0.f, 0.f);
    }
    if (i < GG) out[i] = 0.f;
}

__global__ void zero_a_kernel() {
    int i = blockIdx.x * blockDim.x + threadIdx.x;
    if (i < NN * 16) ((float4*)g_a)[i] = make_float4(0.f, 0.f, 0.f, 0.f);
}

// =====================================================================
// Edge MPN: per 64-edge tile — gather m=[x[dst],x[src],ea], H=relu(m W1+b1),
// out = H W2 + b2, red.v4 scatter into g_a[dst]. Persistent blocks keep
// W1/W2 resident in SMEM. 16x16 threads, 4x4 f32x2 register tiles.
// =====================================================================
__global__ __launch_bounds__(256, 1) void edge_kernel(
    const float* __restrict__ ea, const void* __restrict__ idx,
    const float* __restrict__ W1, const float* __restrict__ b1,
    const float* __restrict__ W2, const float* __restrict__ b2)
{
    extern __shared__ float sm[];
    float* W1s = sm;                 // 160*64 = 10240
    float* W2s = sm + 10240;         // 64*64  = 4096
    float* b1s = sm + 14336;         // 64
    float* b2s = sm + 14400;         // 64
    float* Ms  = sm + 14464;         // 64 * MROW(164)
    float* Hs  = sm + 24960;         // 64 * HROW(72)
    int*   sd  = (int*)(sm + 29568); // 64 dst indices

    int tid = threadIdx.x;
    for (int i = tid; i < 10240; i += 256) W1s[i] = W1[i];
    for (int i = tid; i < 4096; i += 256)  W2s[i] = W2[i];
    if (tid < 64) { b1s[tid] = b1[tid]; b2s[tid] = b2[tid]; }

    const int is64 = g_idx64;
    const long long* i64 = (const long long*)idx;
    const int*       i32 = (const int*)idx;
    const int tx = tid & 15, ty = tid >> 4;
    const int el = tid >> 2, q  = tid & 3;

    for (int tile = blockIdx.x; tile < EE / 64; tile += gridDim.x) {
        int eb = tile * 64;
        __syncthreads();  // protects Ms/Hs/sd reuse; also orders weight staging (1st iter)

        if (tid < 64)
            sd[tid] = is64 ? (int)i64[EE + eb + tid] : i32[EE + eb + tid];
        {
            int eg = eb + el;
            int di = is64 ? (int)i64[EE + eg] : i32[EE + eg];
            int si = is64 ? (int)i64[eg]      : i32[eg];
            const float4* xd = ((const float4*)g_x) + (size_t)di * 16;
            const float4* xs = ((const float4*)g_x) + (size_t)si * 16;
            float4* Mr = (float4*)(Ms + el * MROW);
            #pragma unroll
            for (int i = 0; i < 4; i++) Mr[q * 4 + i] = xd[q * 4 + i];
            #pragma unroll
            for (int i = 0; i < 4; i++) Mr[16 + q * 4 + i] = xs[q * 4 + i];
            const float4* eaf = ((const float4*)ea) + (size_t)eg * 8;
            Mr[32 + q * 2] = eaf[q * 2];
            Mr[33 + q * 2] = eaf[q * 2 + 1];
        }
        __syncthreads();

        // ---- GEMM1: H[e][j] = relu(b1 + sum_k m[e][k] W1[k][j]), K=160 ----
        ull acc[4][2];
        {
            const ull* bp = (const ull*)(b1s + tx * 4);
            ull b0 = bp[0], bv = bp[1];
            #pragma unroll
            for (int i = 0; i < 4; i++) { acc[i][0] = b0; acc[i][1] = bv; }
        }
        #pragma unroll 2
        for (int k4 = 0; k4 < 160; k4 += 4) {
            float4 A[4];
            #pragma unroll
            for (int i = 0; i < 4; i++)
                A[i] = *(const float4*)(Ms + (ty * 4 + i) * MROW + k4);
            #pragma unroll
            for (int kc = 0; kc < 4; kc++) {
                const ull* wr = (const ull*)(W1s + (k4 + kc) * 64);
                ull w0 = wr[tx * 2], w1 = wr[tx * 2 + 1];
                #pragma unroll
                for (int i = 0; i < 4; i++) {
                    float av = (kc == 0) ? A[i].x : (kc == 1) ? A[i].y : (kc == 2) ? A[i].z : A[i].w;
                    ull ad = dup2(av);
                    fma2(acc[i][0], ad, w0);
                    fma2(acc[i][1], ad, w1);
                }
            }
        }
        #pragma unroll
        for (int i = 0; i < 4; i++) {
            float2 p0 = unpack2(acc[i][0]), p1 = unpack2(acc[i][1]);
            float4 h;
            h.x = fmaxf(p0.x, 0.f); h.y = fmaxf(p0.y, 0.f);
            h.z = fmaxf(p1.x, 0.f); h.w = fmaxf(p1.y, 0.f);
            *(float4*)(Hs + (ty * 4 + i) * HROW + tx * 4) = h;
        }
        __syncthreads();

        // ---- GEMM2: out = b2 + H W2, K=64 ----
        ull acc2[4][2];
        {
            const ull* bp = (const ull*)(b2s + tx * 4);
            ull b0 = bp[0], bv = bp[1];
            #pragma unroll
            for (int i = 0; i < 4; i++) { acc2[i][0] = b0; acc2[i][1] = bv; }
        }
        #pragma unroll 2
        for (int k4 = 0; k4 < 64; k4 += 4) {
            float4 A[4];
            #pragma unroll
            for (int i = 0; i < 4; i++)
                A[i] = *(const float4*)(Hs + (ty * 4 + i) * HROW + k4);
            #pragma unroll
            for (int kc = 0; kc < 4; kc++) {
                const ull* wr = (const ull*)(W2s + (k4 + kc) * 64);
                ull w0 = wr[tx * 2], w1 = wr[tx * 2 + 1];
                #pragma unroll
                for (int i = 0; i < 4; i++) {
                    float av = (kc == 0) ? A[i].x : (kc == 1) ? A[i].y : (kc == 2) ? A[i].z : A[i].w;
                    ull ad = dup2(av);
                    fma2(acc2[i][0], ad, w0);
                    fma2(acc2[i][1], ad, w1);
                }
            }
        }
        // ---- vector scatter-add into g_a[dst] ----
        #pragma unroll
        for (int i = 0; i < 4; i++) {
            float2 p0 = unpack2(acc2[i][0]), p1 = unpack2(acc2[i][1]);
            float* dp = g_a + (size_t)sd[ty * 4 + i] * 64 + tx * 4;
            asm volatile("red.global.add.v4.f32 [%0], {%1,%2,%3,%4};"
                         :: "l"(dp), "f"(p0.x), "f"(p0.y), "f"(p1.x), "f"(p1.y)
                         : "memory");
        }
    }
}

// =====================================================================
// LSTM gates GEMM: gates[n][0:256] = [x|a] @ [Wih;Whh] + (bih+bhh)
// 64-node tiles, full 128x256 weight block resident in SMEM.
// =====================================================================
__global__ __launch_bounds__(256, 1) void gates_kernel(
    const float* __restrict__ Wih, const float* __restrict__ Whh,
    const float* __restrict__ bih, const float* __restrict__ bhh)
{
    extern __shared__ float sm[];
    float* Ws = sm;           // 128 * 256 = 32768
    float* bs = sm + 32768;   // 256
    float* XA = sm + 33024;   // 64 * XROW(132)
    int tid = threadIdx.x;
    for (int i = tid; i < 16384; i += 256) { Ws[i] = Wih[i]; Ws[16384 + i] = Whh[i]; }
    bs[tid] = bih[tid] + bhh[tid];

    const int tx = tid & 15, ty = tid >> 4;
    const int nl = tid >> 2, q  = tid & 3;
    const int ntiles = (NN + 63) / 64;

    for (int tile = blockIdx.x; tile < ntiles; tile += gridDim.x) {
        int nb = tile * 64;
        __syncthreads();
        {
            int ng = nb + nl;
            float4* Xr = (float4*)(XA + nl * XROW);
            if (ng < NN) {
                const float4* xp = ((const float4*)g_x) + (size_t)ng * 16;
                const float4* ap = ((const float4*)g_a) + (size_t)ng * 16;
                #pragma unroll
                for (int i = 0; i < 4; i++) Xr[q * 4 + i] = xp[q * 4 + i];
                #pragma unroll
                for (int i = 0; i < 4; i++) Xr[16 + q * 4 + i] = ap[q * 4 + i];
            } else {
                float4 z = make_float4(0.f, 0.f, 0.f, 0.f);
                #pragma unroll
                for (int i = 0; i < 4; i++) { Xr[q * 4 + i] = z; Xr[16 + q * 4 + i] = z; }
            }
        }
        __syncthreads();

        #pragma unroll 1
        for (int jc = 0; jc < 4; jc++) {   // one gate (64 cols) per pass
            ull acc[4][2];
            {
                const ull* bp = (const ull*)(bs + jc * 64 + tx * 4);
                ull b0 = bp[0], bv = bp[1];
                #pragma unroll
                for (int i = 0; i < 4; i++) { acc[i][0] = b0; acc[i][1] = bv; }
            }
            #pragma unroll 2
            for (int k4 = 0; k4 < 128; k4 += 4) {
                float4 A[4];
                #pragma unroll
                for (int i = 0; i < 4; i++)
                    A[i] = *(const float4*)(XA + (ty * 4 + i) * XROW + k4);
                #pragma unroll
                for (int kc = 0; kc < 4; kc++) {
                    const ull* wr = (const ull*)(Ws + (k4 + kc) * 256 + jc * 64);
                    ull w0 = wr[tx * 2], w1 = wr[tx * 2 + 1];
                    #pragma unroll
                    for (int i = 0; i < 4; i++) {
                        float av = (kc == 0) ? A[i].x : (kc == 1) ? A[i].y : (kc == 2) ? A[i].z : A[i].w;
                        ull ad = dup2(av);
                        fma2(acc[i][0], ad, w0);
                        fma2(acc[i][1], ad, w1);
                    }
                }
            }
            #pragma unroll
            for (int i = 0; i < 4; i++) {
                int ng = nb + ty * 4 + i;
                if (ng < NN) {
                    float2 p0 = unpack2(acc[i][0]), p1 = unpack2(acc[i][1]);
                    *(float4*)(g_gates + (size_t)ng * 256 + jc * 64 + tx * 4) =
                        make_float4(p0.x, p0.y, p1.x, p1.y);
                }
            }
        }
    }
}

// -------- LSTM elementwise update: c' = sig(f)c + sig(i)tanh(g); h = sig(o)tanh(c') --------
__global__ void lstm_kernel() {
    int t = blockIdx.x * blockDim.x + threadIdx.x;
    if (t >= NN * 16) return;
    int n = t >> 4, p = t & 15;
    const float4* gp = (const float4*)(g_gates + (size_t)n * 256);
    float4 gi = gp[p], gf = gp[16 + p], gg = gp[32 + p], go = gp[48 + p];
    float4* cp = ((float4*)g_c) + t;
    float4 c = *cp;
    float4 nc, nh;
    nc.x = sigf(gf.x) * c.x + sigf(gi.x) * tanh_f(gg.x);
    nc.y = sigf(gf.y) * c.y + sigf(gi.y) * tanh_f(gg.y);
    nc.z = sigf(gf.z) * c.z + sigf(gi.z) * tanh_f(gg.z);
    nc.w = sigf(gf.w) * c.w + sigf(gi.w) * tanh_f(gg.w);
    nh.x = sigf(go.x) * tanh_f(nc.x);
    nh.y = sigf(go.y) * tanh_f(nc.y);
    nh.z = sigf(go.z) * tanh_f(nc.z);
    nh.w = sigf(go.w) * tanh_f(nc.w);
    *cp = nc;
    ((float4*)g_x)[t] = nh;
}

// -------- readout: out[g] = sum_n sig(xW_g + b_g) * (xW_f + b_f) --------
__global__ __launch_bounds__(256) void readout_kernel(
    const float* __restrict__ gmW, const float* __restrict__ gmb,
    const float* __restrict__ fmW, const float* __restrict__ fmb,
    float* __restrict__ out)
{
    extern __shared__ float sm[];
    float* Gs = sm;          // 64*50
    float* Fs = sm + 3200;   // 64*50
    float* Gb = sm + 6400;   // 50
    float* Fb = sm + 6450;   // 50
    int tid = threadIdx.x;
    for (int i = tid; i < 3200; i += 256) { Gs[i] = gmW[i]; Fs[i] = fmW[i]; }
    if (tid < GG) { Gb[tid] = gmb[tid]; Fb[tid] = fmb[tid]; }
    __syncthreads();

    int n = blockIdx.x * 256 + tid;
    bool valid = n < NN;
    float xr[64];
    if (valid) {
        const float4* xp = ((const float4*)g_x) + (size_t)n * 16;
        #pragma unroll
        for (int i = 0; i < 16; i++) {
            float4 v = xp[i];
            xr[4 * i] = v.x; xr[4 * i + 1] = v.y; xr[4 * i + 2] = v.z; xr[4 * i + 3] = v.w;
        }
    } else {
        #pragma unroll
        for (int i = 0; i < 64; i++) xr[i] = 0.f;
    }

    #pragma unroll 1
    for (int gp2 = 0; gp2 < 25; gp2++) {
        ull a1 = pack2f(Gb[2 * gp2], Gb[2 * gp2 + 1]);
        ull a2 = pack2f(Fb[2 * gp2], Fb[2 * gp2 + 1]);
        #pragma unroll
        for (int k = 0; k < 64; k++) {
            ull xd = dup2(xr[k]);
            fma2(a1, xd, *(const ull*)(Gs + k * 50 + 2 * gp2));
            fma2(a2, xd, *(const ull*)(Fs + k * 50 + 2 * gp2));
        }
        float2 s1 = unpack2(a1), s2 = unpack2(a2);
        float v0 = valid ? sigf(s1.x) * s2.x : 0.f;
        float v1 = valid ? sigf(s1.y) * s2.y : 0.f;
        #pragma unroll
        for (int o = 16; o > 0; o >>= 1) {
            v0 += __shfl_xor_sync(0xffffffffu, v0, o);
            v1 += __shfl_xor_sync(0xffffffffu, v1, o);
        }
        if ((tid & 31) == 0) {
            atomicAdd(&out[2 * gp2], v0);
            atomicAdd(&out[2 * gp2 + 1], v1);
        }
    }
}

// =====================================================================
extern "C" void kernel_launch(void* const* d_in, const int* in_sizes, int n_in,
                              void* d_out, int out_size)
{
    const float* x  = (const float*)d_in[0];
    const float* ea = (const float*)d_in[1];
    const void*  idx = d_in[2];
    const float* feW1[2] = {(const float*)d_in[3],  (const float*)d_in[11]};
    const float* feb1[2] = {(const float*)d_in[4],  (const float*)d_in[12]};
    const float* feW2[2] = {(const float*)d_in[5],  (const float*)d_in[13]};
    const float* feb2[2] = {(const float*)d_in[6],  (const float*)d_in[14]};
    const float* Wih[2]  = {(const float*)d_in[7],  (const float*)d_in[15]};
    const float* Whh[2]  = {(const float*)d_in[8],  (const float*)d_in[16]};
    const float* bih[2]  = {(const float*)d_in[9],  (const float*)d_in[17]};
    const float* bhh[2]  = {(const float*)d_in[10], (const float*)d_in[18]};
    float* out = (float*)d_out;

    cudaFuncSetAttribute(edge_kernel,   cudaFuncAttributeMaxDynamicSharedMemorySize, 118784);
    cudaFuncSetAttribute(gates_kernel,  cudaFuncAttributeMaxDynamicSharedMemorySize, 166144);
    cudaFuncSetAttribute(readout_kernel, cudaFuncAttributeMaxDynamicSharedMemorySize, 26112);

    detect_kernel<<<1, 32>>>((const int*)idx);
    init_kernel<<<(NN * 16 + 255) / 256, 256>>>((const float4*)x, out);

    for (int s = 0; s < 2; s++) {
        zero_a_kernel<<<(NN * 16 + 255) / 256, 256>>>();
        edge_kernel<<<148, 256, 118784>>>(ea, idx, feW1[s], feb1[s], feW2[s], feb2[s]);
        gates_kernel<<<148, 256, 166144>>>(Wih[s], Whh[s], bih[s], bhh[s]);
        lstm_kernel<<<(NN * 16 + 255) / 256, 256>>>();
    }

    readout_kernel<<<(NN + 255) / 256, 256, 26112>>>(
        (const float*)d_in[19], (const float*)d_in[20],
        (const float*)d_in[21], (const float*)d_in[22], out);
}

// round 2
// speedup vs baseline: 1.2200x; 1.2200x over previous
#include <cuda_runtime.h>

#define NN 50000
#define EE 800000
#define GG 50
#define MROW 164
#define HROW 72
#define XROW 132

typedef unsigned long long ull;

// -------- persistent device scratch --------
__device__ float g_x[NN * 64];
__device__ float g_c[NN * 64];
__device__ float g_a[NN * 64];
__device__ float g_gates[NN * 256];
__device__ int   g_idx64;

// -------- packed f32x2 helpers --------
__device__ __forceinline__ ull dup2(float x) {
    ull r; asm("mov.b64 %0, {%1,%1};" : "=l"(r) : "f"(x)); return r;
}
__device__ __forceinline__ ull pack2f(float x, float y) {
    ull r; asm("mov.b64 %0, {%1,%2};" : "=l"(r) : "f"(x), "f"(y)); return r;
}
__device__ __forceinline__ void fma2(ull& d, ull a, ull b) {
    asm("fma.rn.f32x2 %0, %1, %2, %0;" : "+l"(d) : "l"(a), "l"(b));
}
__device__ __forceinline__ float2 unpack2(ull v) {
    float lo, hi; asm("mov.b64 {%0,%1}, %2;" : "=f"(lo), "=f"(hi) : "l"(v));
    return make_float2(lo, hi);
}

__device__ __forceinline__ float sigf(float x) { return 1.f / (1.f + __expf(-x)); }
__device__ __forceinline__ float tanh_f(float x) {
    float t = __expf(-2.f * fabsf(x));
    float r = (1.f - t) / (1.f + t);
    return copysignf(r, x);
}

// -------- parallel dtype detection for edge_index --------
__global__ void detect_kernel(const int* __restrict__ raw) {
    __shared__ int cnt;
    if (threadIdx.x == 0) cnt = 0;
    __syncthreads();
    int z = 0;
    for (int j = threadIdx.x; j < 1024; j += 256) z += (raw[2 * j + 1] == 0);
    #pragma unroll
    for (int o = 16; o > 0; o >>= 1) z += __shfl_xor_sync(0xffffffffu, z, o);
    if ((threadIdx.x & 31) == 0) atomicAdd(&cnt, z);
    __syncthreads();
    if (threadIdx.x == 0) g_idx64 = (cnt > 512) ? 1 : 0;
}

// -------- init: copy x -> g_x, zero g_c & g_a, zero d_out --------
__global__ void init_kernel(const float4* __restrict__ x, float* __restrict__ out) {
    int i = blockIdx.x * blockDim.x + threadIdx.x;
    if (i < NN * 16) {
        ((float4*)g_x)[i] = x[i];
        float4 z = make_float4(0.f, 0.f, 0.f, 0.f);
        ((float4*)g_c)[i] = z;
        ((float4*)g_a)[i] = z;
    }
    if (i < GG) out[i] = 0.f;
}

// =====================================================================
// Edge MPN — warp-closed pipeline: each warp owns 8 edges end-to-end.
// gather -> GEMM1(relu) -> GEMM2 -> red.v4 scatter, only __syncwarp().
// 512 threads/block, weights resident in SMEM (staged once).
// =====================================================================
__global__ __launch_bounds__(512, 1) void edge_kernel(
    const float* __restrict__ ea, const void* __restrict__ idx,
    const float* __restrict__ W1, const float* __restrict__ b1,
    const float* __restrict__ W2, const float* __restrict__ b2)
{
    extern __shared__ float sm[];
    float* W1s = sm;                 // 160*64
    float* W2s = sm + 10240;         // 64*64
    float* b1s = sm + 14336;         // 64
    float* b2s = sm + 14400;         // 64
    float* Ms  = sm + 14464;         // 16 warps * 8 * MROW = 20992
    float* Hs  = sm + 35456;         // 16 warps * 8 * HROW = 9216
    int*   sd  = (int*)(sm + 44672); // 128

    int tid = threadIdx.x;
    for (int i = tid; i < 10240; i += 512) W1s[i] = W1[i];
    for (int i = tid; i < 4096; i += 512)  W2s[i] = W2[i];
    if (tid < 64) { b1s[tid] = b1[tid]; b2s[tid] = b2[tid]; }
    __syncthreads();   // weights visible to all warps; last block barrier

    const int is64 = g_idx64;
    const long long* i64 = (const long long*)idx;
    const int*       i32 = (const int*)idx;

    const int wid  = tid >> 5;
    const int lane = tid & 31;
    const int tx   = lane & 15;      // 16 column groups of 4
    const int ty2  = lane >> 4;      // 2 row groups of 4 (8 rows/warp)
    const int el   = lane >> 2;      // edge within group (0..7)
    const int q    = lane & 3;       // quarter of the row

    float* Mw = Ms + wid * 8 * MROW;
    float* Hw = Hs + wid * 8 * HROW;
    int*   sw = sd + wid * 8;

    for (int grp = blockIdx.x * 16 + wid; grp < EE / 8; grp += gridDim.x * 16) {
        int eb = grp * 8;
        __syncwarp();  // Mw/Hw/sw reuse from previous iteration

        // ---- gather m = [x[dst] | x[src] | ea] into Mw (8 x 160) ----
        {
            int eg = eb + el;
            int di = is64 ? (int)i64[EE + eg] : i32[EE + eg];
            int si = is64 ? (int)i64[eg]      : i32[eg];
            if (q == 0) sw[el] = di;
            const float4* xd = ((const float4*)g_x) + (size_t)di * 16;
            const float4* xs = ((const float4*)g_x) + (size_t)si * 16;
            float4* Mr = (float4*)(Mw + el * MROW);
            #pragma unroll
            for (int i = 0; i < 4; i++) Mr[q * 4 + i] = xd[q * 4 + i];
            #pragma unroll
            for (int i = 0; i < 4; i++) Mr[16 + q * 4 + i] = xs[q * 4 + i];
            const float4* eaf = ((const float4*)ea) + (size_t)eg * 8;
            Mr[32 + q * 2] = eaf[q * 2];
            Mr[33 + q * 2] = eaf[q * 2 + 1];
        }
        __syncwarp();

        // ---- GEMM1: H = relu(m W1 + b1), K=160 ----
        ull acc[4][2];
        {
            const ull* bp = (const ull*)(b1s + tx * 4);
            ull b0 = bp[0], bv = bp[1];
            #pragma unroll
            for (int i = 0; i < 4; i++) { acc[i][0] = b0; acc[i][1] = bv; }
        }
        #pragma unroll 2
        for (int k4 = 0; k4 < 160; k4 += 4) {
            float4 A[4];
            #pragma unroll
            for (int i = 0; i < 4; i++)
                A[i] = *(const float4*)(Mw + (ty2 * 4 + i) * MROW + k4);
            #pragma unroll
            for (int kc = 0; kc < 4; kc++) {
                const ull* wr = (const ull*)(W1s + (k4 + kc) * 64);
                ull w0 = wr[tx * 2], w1 = wr[tx * 2 + 1];
                #pragma unroll
                for (int i = 0; i < 4; i++) {
                    float av = (kc == 0) ? A[i].x : (kc == 1) ? A[i].y : (kc == 2) ? A[i].z : A[i].w;
                    ull ad = dup2(av);
                    fma2(acc[i][0], ad, w0);
                    fma2(acc[i][1], ad, w1);
                }
            }
        }
        #pragma unroll
        for (int i = 0; i < 4; i++) {
            float2 p0 = unpack2(acc[i][0]), p1 = unpack2(acc[i][1]);
            float4 h;
            h.x = fmaxf(p0.x, 0.f); h.y = fmaxf(p0.y, 0.f);
            h.z = fmaxf(p1.x, 0.f); h.w = fmaxf(p1.y, 0.f);
            *(float4*)(Hw + (ty2 * 4 + i) * HROW + tx * 4) = h;
        }
        __syncwarp();

        // ---- GEMM2: out = H W2 + b2, K=64; then scatter ----
        ull acc2[4][2];
        {
            const ull* bp = (const ull*)(b2s + tx * 4);
            ull b0 = bp[0], bv = bp[1];
            #pragma unroll
            for (int i = 0; i < 4; i++) { acc2[i][0] = b0; acc2[i][1] = bv; }
        }
        #pragma unroll 2
        for (int k4 = 0; k4 < 64; k4 += 4) {
            float4 A[4];
            #pragma unroll
            for (int i = 0; i < 4; i++)
                A[i] = *(const float4*)(Hw + (ty2 * 4 + i) * HROW + k4);
            #pragma unroll
            for (int kc = 0; kc < 4; kc++) {
                const ull* wr = (const ull*)(W2s + (k4 + kc) * 64);
                ull w0 = wr[tx * 2], w1 = wr[tx * 2 + 1];
                #pragma unroll
                for (int i = 0; i < 4; i++) {
                    float av = (kc == 0) ? A[i].x : (kc == 1) ? A[i].y : (kc == 2) ? A[i].z : A[i].w;
                    ull ad = dup2(av);
                    fma2(acc2[i][0], ad, w0);
                    fma2(acc2[i][1], ad, w1);
                }
            }
        }
        #pragma unroll
        for (int i = 0; i < 4; i++) {
            float2 p0 = unpack2(acc2[i][0]), p1 = unpack2(acc2[i][1]);
            float* dp = g_a + (size_t)sw[ty2 * 4 + i] * 64 + tx * 4;
            asm volatile("red.global.add.v4.f32 [%0], {%1,%2,%3,%4};"
                         :: "l"(dp), "f"(p0.x), "f"(p0.y), "f"(p1.x), "f"(p1.y)
                         : "memory");
        }
    }
}

// =====================================================================
// LSTM gates GEMM — warp-closed: each warp owns 8 nodes per group.
// gates[n] = [x|a] @ [Wih;Whh] + (bih+bhh). 512 threads, weights in SMEM.
// =====================================================================
__global__ __launch_bounds__(512, 1) void gates_kernel(
    const float* __restrict__ Wih, const float* __restrict__ Whh,
    const float* __restrict__ bih, const float* __restrict__ bhh)
{
    extern __shared__ float sm[];
    float* Ws = sm;           // 128*256
    float* bs = sm + 32768;   // 256
    float* XA = sm + 33024;   // 16 warps * 8 * XROW = 16896
    int tid = threadIdx.x;
    for (int i = tid; i < 16384; i += 512) { Ws[i] = Wih[i]; Ws[16384 + i] = Whh[i]; }
    if (tid < 256) bs[tid] = bih[tid] + bhh[tid];
    __syncthreads();

    const int wid  = tid >> 5;
    const int lane = tid & 31;
    const int tx   = lane & 15;
    const int ty2  = lane >> 4;
    const int el   = lane >> 2;
    const int q    = lane & 3;
    float* Xw = XA + wid * 8 * XROW;

    for (int grp = blockIdx.x * 16 + wid; grp < NN / 8; grp += gridDim.x * 16) {
        int nb = grp * 8;
        __syncwarp();
        {
            int ng = nb + el;
            const float4* xp = ((const float4*)g_x) + (size_t)ng * 16;
            const float4* ap = ((const float4*)g_a) + (size_t)ng * 16;
            float4* Xr = (float4*)(Xw + el * XROW);
            #pragma unroll
            for (int i = 0; i < 4; i++) Xr[q * 4 + i] = xp[q * 4 + i];
            #pragma unroll
            for (int i = 0; i < 4; i++) Xr[16 + q * 4 + i] = ap[q * 4 + i];
        }
        __syncwarp();

        #pragma unroll 1
        for (int jc = 0; jc < 4; jc++) {
            ull acc[4][2];
            {
                const ull* bp = (const ull*)(bs + jc * 64 + tx * 4);
                ull b0 = bp[0], bv = bp[1];
                #pragma unroll
                for (int i = 0; i < 4; i++) { acc[i][0] = b0; acc[i][1] = bv; }
            }
            #pragma unroll 2
            for (int k4 = 0; k4 < 128; k4 += 4) {
                float4 A[4];
                #pragma unroll
                for (int i = 0; i < 4; i++)
                    A[i] = *(const float4*)(Xw + (ty2 * 4 + i) * XROW + k4);
                #pragma unroll
                for (int kc = 0; kc < 4; kc++) {
                    const ull* wr = (const ull*)(Ws + (k4 + kc) * 256 + jc * 64);
                    ull w0 = wr[tx * 2], w1 = wr[tx * 2 + 1];
                    #pragma unroll
                    for (int i = 0; i < 4; i++) {
                        float av = (kc == 0) ? A[i].x : (kc == 1) ? A[i].y : (kc == 2) ? A[i].z : A[i].w;
                        ull ad = dup2(av);
                        fma2(acc[i][0], ad, w0);
                        fma2(acc[i][1], ad, w1);
                    }
                }
            }
            #pragma unroll
            for (int i = 0; i < 4; i++) {
                int ng = nb + ty2 * 4 + i;
                float2 p0 = unpack2(acc[i][0]), p1 = unpack2(acc[i][1]);
                *(float4*)(g_gates + (size_t)ng * 256 + jc * 64 + tx * 4) =
                    make_float4(p0.x, p0.y, p1.x, p1.y);
            }
        }
    }
}

// -------- LSTM elementwise update; also re-zeroes g_a for the next step --------
__global__ void lstm_kernel() {
    int t = blockIdx.x * blockDim.x + threadIdx.x;
    if (t >= NN * 16) return;
    int n = t >> 4, p = t & 15;
    const float4* gp = (const float4*)(g_gates + (size_t)n * 256);
    float4 gi = gp[p], gf = gp[16 + p], gg = gp[32 + p], go = gp[48 + p];
    float4* cp = ((float4*)g_c) + t;
    float4 c = *cp;
    float4 nc, nh;
    nc.x = sigf(gf.x) * c.x + sigf(gi.x) * tanh_f(gg.x);
    nc.y = sigf(gf.y) * c.y + sigf(gi.y) * tanh_f(gg.y);
    nc.z = sigf(gf.z) * c.z + sigf(gi.z) * tanh_f(gg.z);
    nc.w = sigf(gf.w) * c.w + sigf(gi.w) * tanh_f(gg.w);
    nh.x = sigf(go.x) * tanh_f(nc.x);
    nh.y = sigf(go.y) * tanh_f(nc.y);
    nh.z = sigf(go.z) * tanh_f(nc.z);
    nh.w = sigf(go.w) * tanh_f(nc.w);
    *cp = nc;
    ((float4*)g_x)[t] = nh;
    ((float4*)g_a)[t] = make_float4(0.f, 0.f, 0.f, 0.f);
}

// -------- readout: out[g] = sum_n sig(xW_g + b_g) * (xW_f + b_f) --------
__global__ __launch_bounds__(256) void readout_kernel(
    const float* __restrict__ gmW, const float* __restrict__ gmb,
    const float* __restrict__ fmW, const float* __restrict__ fmb,
    float* __restrict__ out)
{
    extern __shared__ float sm[];
    float* Gs = sm;          // 64*50
    float* Fs = sm + 3200;   // 64*50
    float* Gb = sm + 6400;   // 50
    float* Fb = sm + 6450;   // 50
    int tid = threadIdx.x;
    for (int i = tid; i < 3200; i += 256) { Gs[i] = gmW[i]; Fs[i] = fmW[i]; }
    if (tid < GG) { Gb[tid] = gmb[tid]; Fb[tid] = fmb[tid]; }
    __syncthreads();

    int n = blockIdx.x * 256 + tid;
    bool valid = n < NN;
    float xr[64];
    if (valid) {
        const float4* xp = ((const float4*)g_x) + (size_t)n * 16;
        #pragma unroll
        for (int i = 0; i < 16; i++) {
            float4 v = xp[i];
            xr[4 * i] = v.x; xr[4 * i + 1] = v.y; xr[4 * i + 2] = v.z; xr[4 * i + 3] = v.w;
        }
    } else {
        #pragma unroll
        for (int i = 0; i < 64; i++) xr[i] = 0.f;
    }

    #pragma unroll 1
    for (int gp2 = 0; gp2 < 25; gp2++) {
        ull a1 = pack2f(Gb[2 * gp2], Gb[2 * gp2 + 1]);
        ull a2 = pack2f(Fb[2 * gp2], Fb[2 * gp2 + 1]);
        #pragma unroll
        for (int k = 0; k < 64; k++) {
            ull xd = dup2(xr[k]);
            fma2(a1, xd, *(const ull*)(Gs + k * 50 + 2 * gp2));
            fma2(a2, xd, *(const ull*)(Fs + k * 50 + 2 * gp2));
        }
        float2 s1 = unpack2(a1), s2 = unpack2(a2);
        float v0 = valid ? sigf(s1.x) * s2.x : 0.f;
        float v1 = valid ? sigf(s1.y) * s2.y : 0.f;
        #pragma unroll
        for (int o = 16; o > 0; o >>= 1) {
            v0 += __shfl_xor_sync(0xffffffffu, v0, o);
            v1 += __shfl_xor_sync(0xffffffffu, v1, o);
        }
        if ((tid & 31) == 0) {
            atomicAdd(&out[2 * gp2], v0);
            atomicAdd(&out[2 * gp2 + 1], v1);
        }
    }
}

// =====================================================================
extern "C" void kernel_launch(void* const* d_in, const int* in_sizes, int n_in,
                              void* d_out, int out_size)
{
    const float* x  = (const float*)d_in[0];
    const float* ea = (const float*)d_in[1];
    const void*  idx = d_in[2];
    const float* feW1[2] = {(const float*)d_in[3],  (const float*)d_in[11]};
    const float* feb1[2] = {(const float*)d_in[4],  (const float*)d_in[12]};
    const float* feW2[2] = {(const float*)d_in[5],  (const float*)d_in[13]};
    const float* feb2[2] = {(const float*)d_in[6],  (const float*)d_in[14]};
    const float* Wih[2]  = {(const float*)d_in[7],  (const float*)d_in[15]};
    const float* Whh[2]  = {(const float*)d_in[8],  (const float*)d_in[16]};
    const float* bih[2]  = {(const float*)d_in[9],  (const float*)d_in[17]};
    const float* bhh[2]  = {(const float*)d_in[10], (const float*)d_in[18]};
    float* out = (float*)d_out;

    cudaFuncSetAttribute(edge_kernel,    cudaFuncAttributeMaxDynamicSharedMemorySize, 179200);
    cudaFuncSetAttribute(gates_kernel,   cudaFuncAttributeMaxDynamicSharedMemorySize, 199680);
    cudaFuncSetAttribute(readout_kernel, cudaFuncAttributeMaxDynamicSharedMemorySize, 26112);

    detect_kernel<<<1, 256>>>((const int*)idx);
    init_kernel<<<(NN * 16 + 255) / 256, 256>>>((const float4*)x, out);

    for (int s = 0; s < 2; s++) {
        edge_kernel<<<148, 512, 179200>>>(ea, idx, feW1[s], feb1[s], feW2[s], feb2[s]);
        gates_kernel<<<148, 512, 199680>>>(Wih[s], Whh[s], bih[s], bhh[s]);
        lstm_kernel<<<(NN * 16 + 255) / 256, 256>>>();
    }

    readout_kernel<<<(NN + 255) / 256, 256, 26112>>>(
        (const float*)d_in[19], (const float*)d_in[20],
        (const float*)d_in[21], (const float*)d_in[22], out);
}

// round 4
// speedup vs baseline: 1.8089x; 1.4827x over previous
#include <cuda_runtime.h>
#include <cstdint>

#define NN 50000
#define EE 800000
#define GG 50
#define XROW 132

// edge kernel geometry
#define MS 164    // M row stride (floats)
#define HS 68     // H row stride (floats)
#define W1S 168   // W1T row stride (halves)
#define W2S 72    // W2T row stride (halves)

#define OFF_W1H 0
#define OFF_W1L 21504
#define OFF_W2H 43008
#define OFF_W2L 52224
#define OFF_B1  61440
#define OFF_B2  61696
#define OFF_SD  61952
#define OFF_M   62464
#define OFF_H   146432
#define EDGE_SMEM 181248

typedef unsigned long long ull;

// -------- persistent device scratch --------
__device__ float g_x[NN * 64];
__device__ float g_c[NN * 64];
__device__ float g_a[NN * 64];
__device__ float g_gates[NN * 256];
__device__ int   g_idx64;

// -------- packed f32x2 helpers (for gates/readout kernels) --------
__device__ __forceinline__ ull dup2(float x) {
    ull r; asm("mov.b64 %0, {%1,%1};" : "=l"(r) : "f"(x)); return r;
}
__device__ __forceinline__ ull pack2f(float x, float y) {
    ull r; asm("mov.b64 %0, {%1,%2};" : "=l"(r) : "f"(x), "f"(y)); return r;
}
__device__ __forceinline__ void fma2(ull& d, ull a, ull b) {
    asm("fma.rn.f32x2 %0, %1, %2, %0;" : "+l"(d) : "l"(a), "l"(b));
}
__device__ __forceinline__ float2 unpack2(ull v) {
    float lo, hi; asm("mov.b64 {%0,%1}, %2;" : "=f"(lo), "=f"(hi) : "l"(v));
    return make_float2(lo, hi);
}

__device__ __forceinline__ float sigf(float x) { return 1.f / (1.f + __expf(-x)); }
__device__ __forceinline__ float tanh_f(float x) {
    float t = __expf(-2.f * fabsf(x));
    float r = (1.f - t) / (1.f + t);
    return copysignf(r, x);
}

// -------- bf16 split helpers --------
// pack (v0 -> low, v1 -> high) rounded to bf16; lo = residuals packed same way
__device__ __forceinline__ void bsplit2(float v0, float v1, uint32_t& h, uint32_t& l) {
    asm("cvt.rn.bf16x2.f32 %0, %2, %1;" : "=r"(h) : "f"(v0), "f"(v1));
    float r0 = v0 - __uint_as_float(h << 16);
    float r1 = v1 - __uint_as_float(h & 0xffff0000u);
    asm("cvt.rn.bf16x2.f32 %0, %2, %1;" : "=r"(l) : "f"(r0), "f"(r1));
}
__device__ __forceinline__ void bsplit1(float v, uint16_t& h, uint16_t& l) {
    uint32_t p;
    asm("cvt.rn.bf16x2.f32 %0, %1, %1;" : "=r"(p) : "f"(v));
    h = (uint16_t)(p & 0xffffu);
    float r = v - __uint_as_float(p << 16);
    asm("cvt.rn.bf16x2.f32 %0, %1, %1;" : "=r"(p) : "f"(r));
    l = (uint16_t)(p & 0xffffu);
}

// bf16 tensor-core mma, fp32 accum (baseline PTX, works on compute_103)
__device__ __forceinline__ void mma16816(float* c, const uint32_t* A, uint32_t b0, uint32_t b1) {
    asm volatile("mma.sync.aligned.m16n8k16.row.col.f32.bf16.bf16.f32 "
                 "{%0,%1,%2,%3}, {%4,%5,%6,%7}, {%8,%9}, {%0,%1,%2,%3};"
                 : "+f"(c[0]), "+f"(c[1]), "+f"(c[2]), "+f"(c[3])
                 : "r"(A[0]), "r"(A[1]), "r"(A[2]), "r"(A[3]), "r"(b0), "r"(b1));
}

// -------- parallel dtype detection for edge_index --------
__global__ void detect_kernel(const int* __restrict__ raw) {
    __shared__ int cnt;
    if (threadIdx.x == 0) cnt = 0;
    __syncthreads();
    int z = 0;
    for (int j = threadIdx.x; j < 1024; j += 256) z += (raw[2 * j + 1] == 0);
    #pragma unroll
    for (int o = 16; o > 0; o >>= 1) z += __shfl_xor_sync(0xffffffffu, z, o);
    if ((threadIdx.x & 31) == 0) atomicAdd(&cnt, z);
    __syncthreads();
    if (threadIdx.x == 0) g_idx64 = (cnt > 512) ? 1 : 0;
}

// -------- init --------
__global__ void init_kernel(const float4* __restrict__ x, float* __restrict__ out) {
    int i = blockIdx.x * blockDim.x + threadIdx.x;
    if (i < NN * 16) {
        ((float4*)g_x)[i] = x[i];
        float4 z = make_float4(0.f, 0.f, 0.f, 0.f);
        ((float4*)g_c)[i] = z;
        ((float4*)g_a)[i] = z;
    }
    if (i < GG) out[i] = 0.f;
}

// =====================================================================
// Edge MPN via mma.sync bf16 3-way split. Warp-closed 16-edge tiles.
// gather(fp32) -> GEMM1 relu -> GEMM2 -> red.v4 scatter.
// =====================================================================
__global__ __launch_bounds__(256, 1) void edge_kernel(
    const float* __restrict__ ea, const void* __restrict__ idx,
    const float* __restrict__ W1, const float* __restrict__ b1,
    const float* __restrict__ W2, const float* __restrict__ b2)
{
    extern __shared__ char sm[];
    uint16_t* w1h = (uint16_t*)(sm + OFF_W1H);
    uint16_t* w1l = (uint16_t*)(sm + OFF_W1L);
    uint16_t* w2h = (uint16_t*)(sm + OFF_W2H);
    uint16_t* w2l = (uint16_t*)(sm + OFF_W2L);
    float* b1s = (float*)(sm + OFF_B1);
    float* b2s = (float*)(sm + OFF_B2);

    const int tid = threadIdx.x;

    // ---- stage weights: W^T bf16 hi/lo ----
    for (int i = tid; i < 10240; i += 256) {
        int k = i >> 6, n = i & 63;
        uint16_t h, l; bsplit1(W1[i], h, l);
        int off = n * W1S + k;
        w1h[off] = h; w1l[off] = l;
    }
    for (int i = tid; i < 4096; i += 256) {
        int k = i >> 6, n = i & 63;
        uint16_t h, l; bsplit1(W2[i], h, l);
        int off = n * W2S + k;
        w2h[off] = h; w2l[off] = l;
    }
    if (tid < 64) { b1s[tid] = b1[tid]; b2s[tid] = b2[tid]; }
    __syncthreads();

    const int is64 = g_idx64;
    const long long* i64 = (const long long*)idx;
    const int*       i32 = (const int*)idx;

    const int wid  = tid >> 5;
    const int lane = tid & 31;
    const int r    = lane >> 2;   // 0..7
    const int q    = lane & 3;    // 0..3
    const int el   = lane >> 1;   // edge row 0..15
    const int hh   = lane & 1;    // 0: dst half, 1: src half

    float* Mw = (float*)(sm + OFF_M) + wid * 16 * MS;
    float* Hw = (float*)(sm + OFF_H) + wid * 16 * HS;
    int*   sd = (int*)(sm + OFF_SD) + wid * 16;

    for (int grp = blockIdx.x * 8 + wid; grp < EE / 16; grp += gridDim.x * 8) {
        int eb = grp * 16;
        __syncwarp();

        // ---- gather m = [x[dst] | x[src] | ea] into Mw fp32 ----
        {
            int eg = eb + el;
            int node = is64 ? (int)i64[hh ? eg : (EE + eg)]
                            : i32[hh ? eg : (EE + eg)];
            if (hh == 0) sd[el] = node;
            const float4* xp = ((const float4*)g_x) + (size_t)node * 16;
            float4* Mr = (float4*)(Mw + el * MS) + hh * 16;
            #pragma unroll
            for (int i = 0; i < 16; i++) Mr[i] = xp[i];
            const float4* ep = ((const float4*)ea) + (size_t)eg * 8 + hh * 4;
            float4* Er = (float4*)(Mw + el * MS + 128) + hh * 4;
            #pragma unroll
            for (int i = 0; i < 4; i++) Er[i] = ep[i];
        }
        __syncwarp();

        // ---- GEMM1: H = relu(M @ W1 + b1), K=160, 16x64 out per warp ----
        float acc[8][4];
        #pragma unroll
        for (int nt = 0; nt < 8; nt++) {
            float bb0 = b1s[nt * 8 + 2 * q], bb1 = b1s[nt * 8 + 2 * q + 1];
            acc[nt][0] = bb0; acc[nt][1] = bb1; acc[nt][2] = bb0; acc[nt][3] = bb1;
        }
        #pragma unroll 2
        for (int kt = 0; kt < 160; kt += 16) {
            const float* m0 = Mw + r * MS + kt + 2 * q;
            float2 p0 = *(const float2*)m0;
            float2 p1 = *(const float2*)(m0 + 8 * MS);
            float2 p2 = *(const float2*)(m0 + 8);
            float2 p3 = *(const float2*)(m0 + 8 * MS + 8);
            uint32_t Ah[4], Al[4];
            bsplit2(p0.x, p0.y, Ah[0], Al[0]);
            bsplit2(p1.x, p1.y, Ah[1], Al[1]);
            bsplit2(p2.x, p2.y, Ah[2], Al[2]);
            bsplit2(p3.x, p3.y, Ah[3], Al[3]);
            #pragma unroll
            for (int nt = 0; nt < 8; nt++) {
                const uint16_t* ph = w1h + (nt * 8 + r) * W1S + kt + 2 * q;
                const uint16_t* pl = w1l + (nt * 8 + r) * W1S + kt + 2 * q;
                uint32_t bh0 = *(const uint32_t*)ph;
                uint32_t bh1 = *(const uint32_t*)(ph + 8);
                uint32_t bl0 = *(const uint32_t*)pl;
                uint32_t bl1 = *(const uint32_t*)(pl + 8);
                mma16816(acc[nt], Ah, bh0, bh1);
                mma16816(acc[nt], Al, bh0, bh1);
                mma16816(acc[nt], Ah, bl0, bl1);
            }
        }
        // relu -> Hw
        #pragma unroll
        for (int nt = 0; nt < 8; nt++) {
            *(float2*)(Hw + r * HS + nt * 8 + 2 * q) =
                make_float2(fmaxf(acc[nt][0], 0.f), fmaxf(acc[nt][1], 0.f));
            *(float2*)(Hw + (r + 8) * HS + nt * 8 + 2 * q) =
                make_float2(fmaxf(acc[nt][2], 0.f), fmaxf(acc[nt][3], 0.f));
        }
        __syncwarp();

        // ---- GEMM2: D2 = H @ W2 + b2, K=64 ----
        float acc2[8][4];
        #pragma unroll
        for (int nt = 0; nt < 8; nt++) {
            float bb0 = b2s[nt * 8 + 2 * q], bb1 = b2s[nt * 8 + 2 * q + 1];
            acc2[nt][0] = bb0; acc2[nt][1] = bb1; acc2[nt][2] = bb0; acc2[nt][3] = bb1;
        }
        #pragma unroll
        for (int kt = 0; kt < 64; kt += 16) {
            const float* h0 = Hw + r * HS + kt + 2 * q;
            float2 p0 = *(const float2*)h0;
            float2 p1 = *(const float2*)(h0 + 8 * HS);
            float2 p2 = *(const float2*)(h0 + 8);
            float2 p3 = *(const float2*)(h0 + 8 * HS + 8);
            uint32_t Ah[4], Al[4];
            bsplit2(p0.x, p0.y, Ah[0], Al[0]);
            bsplit2(p1.x, p1.y, Ah[1], Al[1]);
            bsplit2(p2.x, p2.y, Ah[2], Al[2]);
            bsplit2(p3.x, p3.y, Ah[3], Al[3]);
            #pragma unroll
            for (int nt = 0; nt < 8; nt++) {
                const uint16_t* ph = w2h + (nt * 8 + r) * W2S + kt + 2 * q;
                const uint16_t* pl = w2l + (nt * 8 + r) * W2S + kt + 2 * q;
                uint32_t bh0 = *(const uint32_t*)ph;
                uint32_t bh1 = *(const uint32_t*)(ph + 8);
                uint32_t bl0 = *(const uint32_t*)pl;
                uint32_t bl1 = *(const uint32_t*)(pl + 8);
                mma16816(acc2[nt], Ah, bh0, bh1);
                mma16816(acc2[nt], Al, bh0, bh1);
                mma16816(acc2[nt], Ah, bl0, bl1);
            }
        }
        __syncwarp();   // all Hw reads done before overwrite
        // stage D2 into Hw for vectorized scatter
        #pragma unroll
        for (int nt = 0; nt < 8; nt++) {
            *(float2*)(Hw + r * HS + nt * 8 + 2 * q) = make_float2(acc2[nt][0], acc2[nt][1]);
            *(float2*)(Hw + (r + 8) * HS + nt * 8 + 2 * q) = make_float2(acc2[nt][2], acc2[nt][3]);
        }
        __syncwarp();
        // red.v4 scatter into g_a[dst]
        #pragma unroll
        for (int it = 0; it < 8; it++) {
            int chunk = it * 32 + lane;        // 0..255
            int row = chunk >> 4, c4 = chunk & 15;
            const float* hp = Hw + row * HS + c4 * 4;
            float4 v = *(const float4*)hp;
            float* dp = g_a + (size_t)sd[row] * 64 + c4 * 4;
            asm volatile("red.global.add.v4.f32 [%0], {%1,%2,%3,%4};"
                         :: "l"(dp), "f"(v.x), "f"(v.y), "f"(v.z), "f"(v.w)
                         : "memory");
        }
    }
}

// =====================================================================
// LSTM gates GEMM — warp-closed fp32 FFMA2 (unchanged)
// =====================================================================
__global__ __launch_bounds__(512, 1) void gates_kernel(
    const float* __restrict__ Wih, const float* __restrict__ Whh,
    const float* __restrict__ bih, const float* __restrict__ bhh)
{
    extern __shared__ float smf[];
    float* Ws = smf;
    float* bs = smf + 32768;
    float* XA = smf + 33024;
    int tid = threadIdx.x;
    for (int i = tid; i < 16384; i += 512) { Ws[i] = Wih[i]; Ws[16384 + i] = Whh[i]; }
    if (tid < 256) bs[tid] = bih[tid] + bhh[tid];
    __syncthreads();

    const int wid  = tid >> 5;
    const int lane = tid & 31;
    const int tx   = lane & 15;
    const int ty2  = lane >> 4;
    const int el   = lane >> 2;
    const int q    = lane & 3;
    float* Xw = XA + wid * 8 * XROW;

    for (int grp = blockIdx.x * 16 + wid; grp < NN / 8; grp += gridDim.x * 16) {
        int nb = grp * 8;
        __syncwarp();
        {
            int ng = nb + el;
            const float4* xp = ((const float4*)g_x) + (size_t)ng * 16;
            const float4* ap = ((const float4*)g_a) + (size_t)ng * 16;
            float4* Xr = (float4*)(Xw + el * XROW);
            #pragma unroll
            for (int i = 0; i < 4; i++) Xr[q * 4 + i] = xp[q * 4 + i];
            #pragma unroll
            for (int i = 0; i < 4; i++) Xr[16 + q * 4 + i] = ap[q * 4 + i];
        }
        __syncwarp();

        #pragma unroll 1
        for (int jc = 0; jc < 4; jc++) {
            ull acc[4][2];
            {
                const ull* bp = (const ull*)(bs + jc * 64 + tx * 4);
                ull b0 = bp[0], bv = bp[1];
                #pragma unroll
                for (int i = 0; i < 4; i++) { acc[i][0] = b0; acc[i][1] = bv; }
            }
            #pragma unroll 2
            for (int k4 = 0; k4 < 128; k4 += 4) {
                float4 A[4];
                #pragma unroll
                for (int i = 0; i < 4; i++)
                    A[i] = *(const float4*)(Xw + (ty2 * 4 + i) * XROW + k4);
                #pragma unroll
                for (int kc = 0; kc < 4; kc++) {
                    const ull* wr = (const ull*)(Ws + (k4 + kc) * 256 + jc * 64);
                    ull w0 = wr[tx * 2], w1 = wr[tx * 2 + 1];
                    #pragma unroll
                    for (int i = 0; i < 4; i++) {
                        float av = (kc == 0) ? A[i].x : (kc == 1) ? A[i].y : (kc == 2) ? A[i].z : A[i].w;
                        ull ad = dup2(av);
                        fma2(acc[i][0], ad, w0);
                        fma2(acc[i][1], ad, w1);
                    }
                }
            }
            #pragma unroll
            for (int i = 0; i < 4; i++) {
                int ng = nb + ty2 * 4 + i;
                float2 p0 = unpack2(acc[i][0]), p1 = unpack2(acc[i][1]);
                *(float4*)(g_gates + (size_t)ng * 256 + jc * 64 + tx * 4) =
                    make_float4(p0.x, p0.y, p1.x, p1.y);
            }
        }
    }
}

// -------- LSTM elementwise update; re-zeroes g_a for next step --------
__global__ void lstm_kernel() {
    int t = blockIdx.x * blockDim.x + threadIdx.x;
    if (t >= NN * 16) return;
    int n = t >> 4, p = t & 15;
    const float4* gp = (const float4*)(g_gates + (size_t)n * 256);
    float4 gi = gp[p], gf = gp[16 + p], gg = gp[32 + p], go = gp[48 + p];
    float4* cp = ((float4*)g_c) + t;
    float4 c = *cp;
    float4 nc, nh;
    nc.x = sigf(gf.x) * c.x + sigf(gi.x) * tanh_f(gg.x);
    nc.y = sigf(gf.y) * c.y + sigf(gi.y) * tanh_f(gg.y);
    nc.z = sigf(gf.z) * c.z + sigf(gi.z) * tanh_f(gg.z);
    nc.w = sigf(gf.w) * c.w + sigf(gi.w) * tanh_f(gg.w);
    nh.x = sigf(go.x) * tanh_f(nc.x);
    nh.y = sigf(go.y) * tanh_f(nc.y);
    nh.z = sigf(go.z) * tanh_f(nc.z);
    nh.w = sigf(go.w) * tanh_f(nc.w);
    *cp = nc;
    ((float4*)g_x)[t] = nh;
    ((float4*)g_a)[t] = make_float4(0.f, 0.f, 0.f, 0.f);
}

// -------- readout --------
__global__ __launch_bounds__(256) void readout_kernel(
    const float* __restrict__ gmW, const float* __restrict__ gmb,
    const float* __restrict__ fmW, const float* __restrict__ fmb,
    float* __restrict__ out)
{
    extern __shared__ float smf[];
    float* Gs = smf;
    float* Fs = smf + 3200;
    float* Gb = smf + 6400;
    float* Fb = smf + 6450;
    int tid = threadIdx.x;
    for (int i = tid; i < 3200; i += 256) { Gs[i] = gmW[i]; Fs[i] = fmW[i]; }
    if (tid < GG) { Gb[tid] = gmb[tid]; Fb[tid] = fmb[tid]; }
    __syncthreads();

    int n = blockIdx.x * 256 + tid;
    bool valid = n < NN;
    float xr[64];
    if (valid) {
        const float4* xp = ((const float4*)g_x) + (size_t)n * 16;
        #pragma unroll
        for (int i = 0; i < 16; i++) {
            float4 v = xp[i];
            xr[4 * i] = v.x; xr[4 * i + 1] = v.y; xr[4 * i + 2] = v.z; xr[4 * i + 3] = v.w;
        }
    } else {
        #pragma unroll
        for (int i = 0; i < 64; i++) xr[i] = 0.f;
    }

    #pragma unroll 1
    for (int gp2 = 0; gp2 < 25; gp2++) {
        ull a1 = pack2f(Gb[2 * gp2], Gb[2 * gp2 + 1]);
        ull a2 = pack2f(Fb[2 * gp2], Fb[2 * gp2 + 1]);
        #pragma unroll
        for (int k = 0; k < 64; k++) {
            ull xd = dup2(xr[k]);
            fma2(a1, xd, *(const ull*)(Gs + k * 50 + 2 * gp2));
            fma2(a2, xd, *(const ull*)(Fs + k * 50 + 2 * gp2));
        }
        float2 s1 = unpack2(a1), s2 = unpack2(a2);
        float v0 = valid ? sigf(s1.x) * s2.x : 0.f;
        float v1 = valid ? sigf(s1.y) * s2.y : 0.f;
        #pragma unroll
        for (int o = 16; o > 0; o >>= 1) {
            v0 += __shfl_xor_sync(0xffffffffu, v0, o);
            v1 += __shfl_xor_sync(0xffffffffu, v1, o);
        }
        if ((tid & 31) == 0) {
            atomicAdd(&out[2 * gp2], v0);
            atomicAdd(&out[2 * gp2 + 1], v1);
        }
    }
}

// =====================================================================
extern "C" void kernel_launch(void* const* d_in, const int* in_sizes, int n_in,
                              void* d_out, int out_size)
{
    const float* x  = (const float*)d_in[0];
    const float* ea = (const float*)d_in[1];
    const void*  idx = d_in[2];
    const float* feW1[2] = {(const float*)d_in[3],  (const float*)d_in[11]};
    const float* feb1[2] = {(const float*)d_in[4],  (const float*)d_in[12]};
    const float* feW2[2] = {(const float*)d_in[5],  (const float*)d_in[13]};
    const float* feb2[2] = {(const float*)d_in[6],  (const float*)d_in[14]};
    const float* Wih[2]  = {(const float*)d_in[7],  (const float*)d_in[15]};
    const float* Whh[2]  = {(const float*)d_in[8],  (const float*)d_in[16]};
    const float* bih[2]  = {(const float*)d_in[9],  (const float*)d_in[17]};
    const float* bhh[2]  = {(const float*)d_in[10], (const float*)d_in[18]};
    float* out = (float*)d_out;

    cudaFuncSetAttribute(edge_kernel,    cudaFuncAttributeMaxDynamicSharedMemorySize, EDGE_SMEM);
    cudaFuncSetAttribute(gates_kernel,   cudaFuncAttributeMaxDynamicSharedMemorySize, 199680);
    cudaFuncSetAttribute(readout_kernel, cudaFuncAttributeMaxDynamicSharedMemorySize, 26112);

    detect_kernel<<<1, 256>>>((const int*)idx);
    init_kernel<<<(NN * 16 + 255) / 256, 256>>>((const float4*)x, out);

    for (int s = 0; s < 2; s++) {
        edge_kernel<<<148, 256, EDGE_SMEM>>>(ea, idx, feW1[s], feb1[s], feW2[s], feb2[s]);
        gates_kernel<<<148, 512, 199680>>>(Wih[s], Whh[s], bih[s], bhh[s]);
        lstm_kernel<<<(NN * 16 + 255) / 256, 256>>>();
    }

    readout_kernel<<<(NN + 255) / 256, 256, 26112>>>(
        (const float*)d_in[19], (const float*)d_in[20],
        (const float*)d_in[21], (const float*)d_in[22], out);
}